// round 4
// baseline (speedup 1.0000x reference)
#include <cuda_runtime.h>
#include <cuda_bf16.h>
#include <math.h>
#include <stdint.h>

#define NN 50000
#define EE 800000
#define DD 128
#define BN_EPS 1e-5f
#define NSCAN_BLK 196   // ceil(50000/256)

// ---------------- scratch (static device globals; no allocation) -------------
__device__ float g_deg[NN];
__device__ float g_dis[NN];
__device__ int   g_cnt[NN];
__device__ int   g_off[NN];
__device__ int   g_cur[NN];
__device__ int   g_bsum[256];
__device__ int   g_boff[256];
__device__ int   g_src[EE];
__device__ float g_wn [EE];
__device__ float g_h  [NN * DD];   // emb @ W0
__device__ float g_h1 [NN * DD];   // after agg1 + BN + ELU
__device__ float g_g  [NN * DD];   // h1 @ W1

// ---------------- norm + CSC build ------------------------------------------
__global__ void k_init() {
    int i = blockIdx.x * blockDim.x + threadIdx.x;
    if (i < NN) { g_deg[i] = 1.0f; g_cnt[i] = 0; }   // 1.0 = self-loop weight
}

__global__ void k_deg(const int* __restrict__ col, const float* __restrict__ w) {
    int e = blockIdx.x * blockDim.x + threadIdx.x;
    if (e < EE) {
        int c = col[e];
        atomicAdd(&g_deg[c], w[e]);
        atomicAdd(&g_cnt[c], 1);
    }
}

// per-block sum of counts (scan level 1) + fused deg^-1/2
__global__ void k_bsum() {
    int i = blockIdx.x * 256 + threadIdx.x;
    int v = (i < NN) ? g_cnt[i] : 0;
    if (i < NN) g_dis[i] = rsqrtf(g_deg[i]);   // deg >= 1 (self loop)

#pragma unroll
    for (int o = 16; o > 0; o >>= 1) v += __shfl_down_sync(0xffffffffu, v, o);
    __shared__ int ws[8];
    int lane = threadIdx.x & 31, wid = threadIdx.x >> 5;
    if (lane == 0) ws[wid] = v;
    __syncthreads();
    if (threadIdx.x < 8) {
        int s = ws[threadIdx.x];
#pragma unroll
        for (int o = 4; o > 0; o >>= 1) s += __shfl_down_sync(0xffu, s, o);
        if (threadIdx.x == 0) g_bsum[blockIdx.x] = s;
    }
}

// scan level 2: exclusive scan of the 196 block sums (1 block)
__global__ void k_bscan() {
    __shared__ int sh[256];
    int t = threadIdx.x;
    int v = (t < NSCAN_BLK) ? g_bsum[t] : 0;
    sh[t] = v;
    __syncthreads();
#pragma unroll
    for (int d = 1; d < 256; d <<= 1) {
        int u = (t >= d) ? sh[t - d] : 0;
        __syncthreads();
        sh[t] += u;
        __syncthreads();
    }
    if (t < NSCAN_BLK) g_boff[t] = sh[t] - v;   // exclusive
}

// scan level 3: block-local exclusive scan + global offset -> g_off / g_cur
__global__ void k_scan3() {
    int i = blockIdx.x * 256 + threadIdx.x;
    int v = (i < NN) ? g_cnt[i] : 0;
    int lane = threadIdx.x & 31, wid = threadIdx.x >> 5;

    int x = v;
#pragma unroll
    for (int o = 1; o < 32; o <<= 1) {
        int y = __shfl_up_sync(0xffffffffu, x, o);
        if (lane >= o) x += y;
    }
    __shared__ int wsum[8];
    if (lane == 31) wsum[wid] = x;
    __syncthreads();
    if (threadIdx.x < 8) {
        int s = wsum[threadIdx.x];
#pragma unroll
        for (int o = 1; o < 8; o <<= 1) {
            int y = __shfl_up_sync(0xffu, s, o);
            if ((int)threadIdx.x >= o) s += y;
        }
        wsum[threadIdx.x] = s;
    }
    __syncthreads();
    int base = g_boff[blockIdx.x] + ((wid > 0) ? wsum[wid - 1] : 0);
    int excl = base + x - v;
    if (i < NN) { g_off[i] = excl; g_cur[i] = excl; }
}

__global__ void k_scatter(const int* __restrict__ row, const int* __restrict__ col,
                          const float* __restrict__ w) {
    int e = blockIdx.x * blockDim.x + threadIdx.x;
    if (e < EE) {
        int r = row[e], c = col[e];
        int p = atomicAdd(&g_cur[c], 1);
        g_src[p] = r;
        g_wn[p]  = g_dis[r] * w[e] * g_dis[c];
    }
}

// =============== tensor-core GEMM via mma.sync (bf16 3-pass split) ===========
// C[128tile,128] = A @ W;  A = Ah + Al, W = Wh + Wl (bf16);
// C ~= Ah*Wh + Ah*Wl + Al*Wh accumulated in fp32 (neglected term ~2^-16).
#define PITCH 136                      // bf16 elements per smem row (+8 pad)
#define MAT_BYTES (128 * PITCH * 2)    // 34816
#define SM_TOT (4 * MAT_BYTES)         // 139264

__device__ __forceinline__ uint32_t smem_u32(const void* p) {
    uint32_t a;
    asm("{ .reg .u64 t; cvta.to.shared.u64 t, %1; cvt.u32.u64 %0, t; }"
        : "=r"(a) : "l"(p));
    return a;
}

__device__ __forceinline__ uint32_t pack_bf16x2(float lo, float hi) {
    __nv_bfloat162 t = __floats2bfloat162_rn(lo, hi);   // .x = lo half
    return *(uint32_t*)&t;
}

#define LDSM4(r0, r1, r2, r3, addr) \
    asm volatile("ldmatrix.sync.aligned.m8n8.x4.shared.b16 {%0,%1,%2,%3}, [%4];" \
                 : "=r"(r0), "=r"(r1), "=r"(r2), "=r"(r3) : "r"(addr))

#define LDSM4T(r0, r1, r2, r3, addr) \
    asm volatile("ldmatrix.sync.aligned.m8n8.x4.trans.shared.b16 {%0,%1,%2,%3}, [%4];" \
                 : "=r"(r0), "=r"(r1), "=r"(r2), "=r"(r3) : "r"(addr))

#define MMA16816(c, a0, a1, a2, a3, b0, b1) \
    asm volatile("mma.sync.aligned.m16n8k16.row.col.f32.bf16.bf16.f32 " \
                 "{%0,%1,%2,%3}, {%4,%5,%6,%7}, {%8,%9}, {%0,%1,%2,%3};" \
                 : "+f"((c)[0]), "+f"((c)[1]), "+f"((c)[2]), "+f"((c)[3]) \
                 : "r"(a0), "r"(a1), "r"(a2), "r"(a3), "r"(b0), "r"(b1))

// split a float4 into hi/lo bf16 pairs and store 8 bytes to each buffer
__device__ __forceinline__ void split_store(__nv_bfloat16* H, __nv_bfloat16* L,
                                            int off, float4 v) {
    float hx = __bfloat162float(__float2bfloat16(v.x));
    float hy = __bfloat162float(__float2bfloat16(v.y));
    float hz = __bfloat162float(__float2bfloat16(v.z));
    float hw = __bfloat162float(__float2bfloat16(v.w));
    uint2 hp = make_uint2(pack_bf16x2(hx, hy), pack_bf16x2(hz, hw));
    uint2 lp = make_uint2(pack_bf16x2(v.x - hx, v.y - hy),
                          pack_bf16x2(v.z - hz, v.w - hw));
    *(uint2*)(H + off) = hp;
    *(uint2*)(L + off) = lp;
}

__global__ __launch_bounds__(256) void k_gemm_mma(const float* __restrict__ Aext,
                                                  const float* __restrict__ W,
                                                  int sel) {
    extern __shared__ __align__(16) char sm[];
    __nv_bfloat16* Ah = (__nv_bfloat16*)(sm);
    __nv_bfloat16* Al = (__nv_bfloat16*)(sm + 1 * MAT_BYTES);
    __nv_bfloat16* Wh = (__nv_bfloat16*)(sm + 2 * MAT_BYTES);
    __nv_bfloat16* Wl = (__nv_bfloat16*)(sm + 3 * MAT_BYTES);

    const float* A = Aext ? Aext : g_h1;
    float* C = (sel == 0) ? g_h : g_g;

    int tid = threadIdx.x;
    int lane = tid & 31, wid = tid >> 5;
    int rowBase = blockIdx.x * 128;

    // ---- W -> SMEM hi/lo (row-major [k][n], coalesced gmem reads)
    for (int idx = tid; idx < 4096; idx += 256) {
        int k = idx >> 5, n = (idx & 31) * 4;
        float4 v = *(const float4*)(W + k * 128 + n);
        split_store(Wh, Wl, k * PITCH + n, v);
    }
    // ---- A tile -> SMEM hi/lo
    for (int idx = tid; idx < 4096; idx += 256) {
        int r = idx >> 5, c = (idx & 31) * 4;
        int gr = rowBase + r;
        float4 v = (gr < NN) ? *(const float4*)(A + (size_t)gr * 128 + c)
                             : make_float4(0.f, 0.f, 0.f, 0.f);
        split_store(Ah, Al, r * PITCH + c, v);
    }
    __syncthreads();

    // ---- compute: warp owns rows [m0, m0+16), all 128 cols (16 accум tiles)
    int m0 = wid * 16;
    float acc[16][4];
#pragma unroll
    for (int t = 0; t < 16; t++)
#pragma unroll
        for (int j = 0; j < 4; j++) acc[t][j] = 0.f;

    // ldmatrix lane addressing
    int a_row = m0 + (lane & 15);
    int a_col8 = (lane >> 4) << 3;          // 0 or 8 (k halves)
    int b_krow = lane & 15;                 // k within 16
    int b_n8 = (lane >> 4) << 3;            // 0 or 8 (n halves)

    uint32_t abufs[3] = { smem_u32(Ah), smem_u32(Ah), smem_u32(Al) };
    uint32_t bbufs[3] = { smem_u32(Wh), smem_u32(Wl), smem_u32(Wh) };

#pragma unroll
    for (int p = 0; p < 3; p++) {
        uint32_t ab = abufs[p], bb = bbufs[p];
#pragma unroll
        for (int ks = 0; ks < 8; ks++) {
            int k0 = ks * 16;
            uint32_t a0, a1, a2, a3;
            LDSM4(a0, a1, a2, a3, ab + (uint32_t)(a_row * PITCH + k0 + a_col8) * 2);
#pragma unroll
            for (int nt = 0; nt < 8; nt++) {
                uint32_t b0, b1, b2, b3;
                LDSM4T(b0, b1, b2, b3,
                       bb + (uint32_t)((k0 + b_krow) * PITCH + nt * 16 + b_n8) * 2);
                MMA16816(acc[nt * 2 + 0], a0, a1, a2, a3, b0, b1);
                MMA16816(acc[nt * 2 + 1], a0, a1, a2, a3, b2, b3);
            }
        }
    }

    // ---- epilogue: fragment rows l/4 and l/4+8, cols 2*(l%4)
    int r0 = rowBase + m0 + (lane >> 2);
    int c0 = (lane & 3) * 2;
    bool v0 = r0 < NN, v1 = (r0 + 8) < NN;
#pragma unroll
    for (int t = 0; t < 16; t++) {
        int n = (t >> 1) * 16 + (t & 1) * 8 + c0;
        if (v0) *(float2*)(C + (size_t)r0 * 128 + n) = make_float2(acc[t][0], acc[t][1]);
        if (v1) *(float2*)(C + (size_t)(r0 + 8) * 128 + n) = make_float2(acc[t][2], acc[t][3]);
    }
}

// ---------------- aggregation 1: conv1 + bias + BN + ELU ---------------------
__global__ void k_agg1(const float* __restrict__ b0,
                       const float* __restrict__ gamma,
                       const float* __restrict__ beta,
                       const float* __restrict__ mean,
                       const float* __restrict__ var) {
    int i = blockIdx.x;
    int f = threadIdx.x;
    const float* __restrict__ H = g_h;

    float di = g_dis[i];
    float acc0 = di * di * H[i * DD + f];   // self loop
    float acc1 = 0.f, acc2 = 0.f, acc3 = 0.f;

    int s = g_off[i];
    int n = g_cnt[i];
    int p = 0;
    for (; p + 4 <= n; p += 4) {
        int   i0 = g_src[s + p + 0], i1 = g_src[s + p + 1];
        int   i2 = g_src[s + p + 2], i3 = g_src[s + p + 3];
        float w0 = g_wn[s + p + 0],  w1 = g_wn[s + p + 1];
        float w2 = g_wn[s + p + 2],  w3 = g_wn[s + p + 3];
        acc0 += w0 * H[i0 * DD + f];
        acc1 += w1 * H[i1 * DD + f];
        acc2 += w2 * H[i2 * DD + f];
        acc3 += w3 * H[i3 * DD + f];
    }
    for (; p < n; p++)
        acc0 += g_wn[s + p] * H[g_src[s + p] * DD + f];

    float acc = ((acc0 + acc1) + (acc2 + acc3)) + b0[f];
    float sc  = gamma[f] * rsqrtf(var[f] + BN_EPS);
    float y   = (acc - mean[f]) * sc + beta[f];
    g_h1[i * DD + f] = (y > 0.f) ? y : expm1f(y);
}

// ---------------- aggregation 2 + final fusion mean --------------------------
__global__ void k_agg2(const float* __restrict__ emb,
                       const float* __restrict__ b1,
                       float* __restrict__ out) {
    int i = blockIdx.x;
    int f = threadIdx.x;
    const float* __restrict__ G = g_g;

    float di = g_dis[i];
    float acc0 = di * di * G[i * DD + f];
    float acc1 = 0.f, acc2 = 0.f, acc3 = 0.f;

    int s = g_off[i];
    int n = g_cnt[i];
    int p = 0;
    for (; p + 4 <= n; p += 4) {
        int   i0 = g_src[s + p + 0], i1 = g_src[s + p + 1];
        int   i2 = g_src[s + p + 2], i3 = g_src[s + p + 3];
        float w0 = g_wn[s + p + 0],  w1 = g_wn[s + p + 1];
        float w2 = g_wn[s + p + 2],  w3 = g_wn[s + p + 3];
        acc0 += w0 * G[i0 * DD + f];
        acc1 += w1 * G[i1 * DD + f];
        acc2 += w2 * G[i2 * DD + f];
        acc3 += w3 * G[i3 * DD + f];
    }
    for (; p < n; p++)
        acc0 += g_wn[s + p] * G[g_src[s + p] * DD + f];

    float h2 = ((acc0 + acc1) + (acc2 + acc3)) + b1[f];
    out[i * DD + f] = (emb[i * DD + f] + g_h1[i * DD + f] + h2) * (1.0f / 3.0f);
}

// ---------------- launch -----------------------------------------------------
extern "C" void kernel_launch(void* const* d_in, const int* in_sizes, int n_in,
                              void* d_out, int out_size) {
    const float* emb   = (const float*)d_in[0];
    const int*   ei    = (const int*)  d_in[1];
    const float* ew    = (const float*)d_in[2];
    const float* W0    = (const float*)d_in[3];
    const float* b0    = (const float*)d_in[4];
    const float* W1    = (const float*)d_in[5];
    const float* b1    = (const float*)d_in[6];
    const float* gamma = (const float*)d_in[7];
    const float* beta  = (const float*)d_in[8];
    const float* mean  = (const float*)d_in[9];
    const float* var   = (const float*)d_in[10];
    float* out = (float*)d_out;

    const int* row = ei;        // edge_index[0]
    const int* col = ei + EE;   // edge_index[1]

    const int NB_N = (NN + 255) / 256;
    const int NB_E = (EE + 255) / 256;

    cudaFuncSetAttribute(k_gemm_mma, cudaFuncAttributeMaxDynamicSharedMemorySize, SM_TOT);

    k_init   <<<NB_N, 256>>>();
    k_deg    <<<NB_E, 256>>>(col, ew);
    k_bsum   <<<NSCAN_BLK, 256>>>();
    k_bscan  <<<1, 256>>>();
    k_scan3  <<<NSCAN_BLK, 256>>>();
    k_scatter<<<NB_E, 256>>>(row, col, ew);

    const int NTILE = (NN + 127) / 128;   // 391
    k_gemm_mma<<<NTILE, 256, SM_TOT>>>(emb, W0, 0);      // g_h = emb @ W0
    k_agg1<<<NN, DD>>>(b0, gamma, beta, mean, var);
    k_gemm_mma<<<NTILE, 256, SM_TOT>>>(nullptr, W1, 1);  // g_g = g_h1 @ W1
    k_agg2<<<NN, DD>>>(emb, b1, out);
}

// round 5
// speedup vs baseline: 1.3067x; 1.3067x over previous
#include <cuda_runtime.h>
#include <cuda_bf16.h>
#include <math.h>
#include <stdint.h>

#define NN 50000
#define EE 800000
#define DD 128
#define BN_EPS 1e-5f
#define NSCAN_BLK 196   // ceil(50000/256)

// ---------------- scratch (static device globals; no allocation) -------------
// Self-resetting protocol: g_degx and g_cnt start at 0 (BSS zero-init), are
// accumulated by k_deg, and are reset to 0 by their LAST reader each call
// (g_degx in k_bsum, g_cnt in k_scan3). Every kernel_launch call therefore
// sees identical initial state -> deterministic.
__device__ float g_degx[NN];            // sum of incoming edge weights (no self loop)
__device__ float g_dis[NN];
__device__ int   g_cnt[NN];
__device__ int   g_off[NN];
__device__ int   g_cur[NN];
__device__ int   g_bsum[256];
__device__ int   g_boff[256];
__device__ int   g_src[EE];
__device__ float g_wn [EE];
__device__ float g_h  [NN * DD];        // emb @ W0
__device__ __nv_bfloat16 g_h1h[NN * DD];  // h1 split hi
__device__ __nv_bfloat16 g_h1l[NN * DD];  // h1 split lo
__device__ float g_g  [NN * DD];        // h1 @ W1
__device__ __nv_bfloat16 g_wh[2 * DD * DD];  // W0,W1 split hi  [sel][k][n]
__device__ __nv_bfloat16 g_wl[2 * DD * DD];  // W0,W1 split lo

// ---------------- small helpers ---------------------------------------------
__device__ __forceinline__ uint32_t smem_u32(const void* p) {
    uint32_t a;
    asm("{ .reg .u64 t; cvta.to.shared.u64 t, %1; cvt.u32.u64 %0, t; }"
        : "=r"(a) : "l"(p));
    return a;
}

__device__ __forceinline__ uint32_t pack_bf16x2(float lo, float hi) {
    __nv_bfloat162 t = __floats2bfloat162_rn(lo, hi);   // .x = lo half
    return *(uint32_t*)&t;
}

#define LDSM4(r0, r1, r2, r3, addr) \
    asm volatile("ldmatrix.sync.aligned.m8n8.x4.shared.b16 {%0,%1,%2,%3}, [%4];" \
                 : "=r"(r0), "=r"(r1), "=r"(r2), "=r"(r3) : "r"(addr))

#define LDSM4T(r0, r1, r2, r3, addr) \
    asm volatile("ldmatrix.sync.aligned.m8n8.x4.trans.shared.b16 {%0,%1,%2,%3}, [%4];" \
                 : "=r"(r0), "=r"(r1), "=r"(r2), "=r"(r3) : "r"(addr))

#define MMA16816(c, a0, a1, a2, a3, b0, b1) \
    asm volatile("mma.sync.aligned.m16n8k16.row.col.f32.bf16.bf16.f32 " \
                 "{%0,%1,%2,%3}, {%4,%5,%6,%7}, {%8,%9}, {%0,%1,%2,%3};" \
                 : "+f"((c)[0]), "+f"((c)[1]), "+f"((c)[2]), "+f"((c)[3]) \
                 : "r"(a0), "r"(a1), "r"(a2), "r"(a3), "r"(b0), "r"(b1))

// split a float4 into hi/lo bf16 pairs and store 8 bytes to each buffer
__device__ __forceinline__ void split_store(__nv_bfloat16* H, __nv_bfloat16* L,
                                            int off, float4 v) {
    float hx = __bfloat162float(__float2bfloat16(v.x));
    float hy = __bfloat162float(__float2bfloat16(v.y));
    float hz = __bfloat162float(__float2bfloat16(v.z));
    float hw = __bfloat162float(__float2bfloat16(v.w));
    uint2 hp = make_uint2(pack_bf16x2(hx, hy), pack_bf16x2(hz, hw));
    uint2 lp = make_uint2(pack_bf16x2(v.x - hx, v.y - hy),
                          pack_bf16x2(v.z - hz, v.w - hw));
    *(uint2*)(H + off) = hp;
    *(uint2*)(L + off) = lp;
}

// ---------------- W split (both layers, one launch) --------------------------
__global__ void k_split_w(const float* __restrict__ W0, const float* __restrict__ W1) {
    int idx = blockIdx.x * 256 + threadIdx.x;       // 0..8191 float4s
    if (idx >= 8192) return;
    const float4* src = (const float4*)((idx < 4096) ? W0 : W1);
    int e4 = idx & 4095;
    float4 v = src[e4];
    int off = ((idx < 4096) ? 0 : (DD * DD)) + e4 * 4;
    split_store(g_wh, g_wl, off, v);
}

// ---------------- norm + CSC build ------------------------------------------
__global__ void k_deg(const int* __restrict__ col, const float* __restrict__ w) {
    int e = blockIdx.x * blockDim.x + threadIdx.x;
    if (e < EE) {
        int c = col[e];
        atomicAdd(&g_degx[c], w[e]);
        atomicAdd(&g_cnt[c], 1);
    }
}

// per-block sum of counts (scan level 1) + fused deg^-1/2 + g_degx reset
__global__ void k_bsum() {
    int i = blockIdx.x * 256 + threadIdx.x;
    int v = (i < NN) ? g_cnt[i] : 0;
    if (i < NN) {
        g_dis[i] = rsqrtf(1.0f + g_degx[i]);   // +1.0 = self-loop weight
        g_degx[i] = 0.0f;                      // reset for next call
    }

#pragma unroll
    for (int o = 16; o > 0; o >>= 1) v += __shfl_down_sync(0xffffffffu, v, o);
    __shared__ int ws[8];
    int lane = threadIdx.x & 31, wid = threadIdx.x >> 5;
    if (lane == 0) ws[wid] = v;
    __syncthreads();
    if (threadIdx.x < 8) {
        int s = ws[threadIdx.x];
#pragma unroll
        for (int o = 4; o > 0; o >>= 1) s += __shfl_down_sync(0xffu, s, o);
        if (threadIdx.x == 0) g_bsum[blockIdx.x] = s;
    }
}

// scan level 2: exclusive scan of the 196 block sums (1 block)
__global__ void k_bscan() {
    __shared__ int sh[256];
    int t = threadIdx.x;
    int v = (t < NSCAN_BLK) ? g_bsum[t] : 0;
    sh[t] = v;
    __syncthreads();
#pragma unroll
    for (int d = 1; d < 256; d <<= 1) {
        int u = (t >= d) ? sh[t - d] : 0;
        __syncthreads();
        sh[t] += u;
        __syncthreads();
    }
    if (t < NSCAN_BLK) g_boff[t] = sh[t] - v;   // exclusive
}

// scan level 3: block-local exclusive scan + global offset; resets g_cnt
__global__ void k_scan3() {
    int i = blockIdx.x * 256 + threadIdx.x;
    int v = (i < NN) ? g_cnt[i] : 0;
    int lane = threadIdx.x & 31, wid = threadIdx.x >> 5;

    int x = v;
#pragma unroll
    for (int o = 1; o < 32; o <<= 1) {
        int y = __shfl_up_sync(0xffffffffu, x, o);
        if (lane >= o) x += y;
    }
    __shared__ int wsum[8];
    if (lane == 31) wsum[wid] = x;
    __syncthreads();
    if (threadIdx.x < 8) {
        int s = wsum[threadIdx.x];
#pragma unroll
        for (int o = 1; o < 8; o <<= 1) {
            int y = __shfl_up_sync(0xffu, s, o);
            if ((int)threadIdx.x >= o) s += y;
        }
        wsum[threadIdx.x] = s;
    }
    __syncthreads();
    int base = g_boff[blockIdx.x] + ((wid > 0) ? wsum[wid - 1] : 0);
    int excl = base + x - v;
    if (i < NN) {
        g_off[i] = excl;
        g_cur[i] = excl;
        g_cnt[i] = 0;      // reset for next call (last reader)
    }
}

__global__ void k_scatter(const int* __restrict__ row, const int* __restrict__ col,
                          const float* __restrict__ w) {
    int e = blockIdx.x * blockDim.x + threadIdx.x;
    if (e < EE) {
        int r = row[e], c = col[e];
        int p = atomicAdd(&g_cur[c], 1);
        g_src[p] = r;
        g_wn[p]  = g_dis[r] * w[e] * g_dis[c];
    }
}

// =============== tensor-core GEMM (bf16 3-term split, fused k-loop) ==========
// C[128tile,128] = A @ W;  C ~= Ah*Wh + Ah*Wl + Al*Wh, fp32 accumulate.
// Warp tile 32x64 (2 m16 x 8 n8 accum tiles); fragments shared across terms.
#define PITCH 136                      // bf16 elements per smem row (+8 pad)
#define MAT_BYTES (128 * PITCH * 2)    // 34816
#define SM_TOT (4 * MAT_BYTES)         // 139264

__global__ __launch_bounds__(256) void k_gemm_mma(const float* __restrict__ Af,
                                                  int sel) {
    extern __shared__ __align__(16) char sm[];
    __nv_bfloat16* Ah = (__nv_bfloat16*)(sm);
    __nv_bfloat16* Al = (__nv_bfloat16*)(sm + 1 * MAT_BYTES);
    __nv_bfloat16* Wh = (__nv_bfloat16*)(sm + 2 * MAT_BYTES);
    __nv_bfloat16* Wl = (__nv_bfloat16*)(sm + 3 * MAT_BYTES);

    float* C = (sel == 0) ? g_h : g_g;
    const __nv_bfloat16* WHs = g_wh + sel * (DD * DD);
    const __nv_bfloat16* WLs = g_wl + sel * (DD * DD);

    int tid = threadIdx.x;
    int lane = tid & 31, wid = tid >> 5;
    int rowBase = blockIdx.x * 128;

    // ---- W tiles: straight bf16 copy (pre-split)
#pragma unroll
    for (int it = 0; it < 8; it++) {
        int idx = tid + it * 256;            // 0..2047 uint4s
        int k = idx >> 4, n = (idx & 15) * 8;
        uint4 vh = *(const uint4*)(WHs + k * 128 + n);
        uint4 vl = *(const uint4*)(WLs + k * 128 + n);
        *(uint4*)(Wh + k * PITCH + n) = vh;
        *(uint4*)(Wl + k * PITCH + n) = vl;
    }

    // ---- A tiles
    if (sel == 0) {
        // fp32 source (emb): split in-kernel
#pragma unroll
        for (int it = 0; it < 16; it++) {
            int idx = tid + it * 256;        // 0..4095 float4s
            int r = idx >> 5, c = (idx & 31) * 4;
            int gr = rowBase + r;
            float4 v = (gr < NN) ? *(const float4*)(Af + (size_t)gr * 128 + c)
                                 : make_float4(0.f, 0.f, 0.f, 0.f);
            split_store(Ah, Al, r * PITCH + c, v);
        }
    } else {
        // pre-split bf16 source (h1)
        const uint4 zz = make_uint4(0, 0, 0, 0);
#pragma unroll
        for (int it = 0; it < 8; it++) {
            int idx = tid + it * 256;        // 0..2047 uint4s
            int r = idx >> 4, n = (idx & 15) * 8;
            int gr = rowBase + r;
            uint4 vh = zz, vl = zz;
            if (gr < NN) {
                vh = *(const uint4*)(g_h1h + (size_t)gr * 128 + n);
                vl = *(const uint4*)(g_h1l + (size_t)gr * 128 + n);
            }
            *(uint4*)(Ah + r * PITCH + n) = vh;
            *(uint4*)(Al + r * PITCH + n) = vl;
        }
    }
    __syncthreads();

    // ---- compute: warp (wid&3 -> m strip, wid>>2 -> n strip)
    int m0 = (wid & 3) * 32;
    int n0 = (wid >> 2) * 64;

    float acc[2][8][4];
#pragma unroll
    for (int mt = 0; mt < 2; mt++)
#pragma unroll
        for (int j = 0; j < 8; j++)
#pragma unroll
            for (int q = 0; q < 4; q++) acc[mt][j][q] = 0.f;

    uint32_t AhB = smem_u32(Ah), AlB = smem_u32(Al);
    uint32_t WhB = smem_u32(Wh), WlB = smem_u32(Wl);
    int a_r = lane & 15, a_c8 = (lane >> 4) << 3;
    int b_k = lane & 15, b_n8 = (lane >> 4) << 3;

#pragma unroll
    for (int ks = 0; ks < 8; ks++) {
        int k0 = ks * 16;
        uint32_t ah[2][4], al[2][4];
#pragma unroll
        for (int mt = 0; mt < 2; mt++) {
            uint32_t aoff = (uint32_t)((m0 + mt * 16 + a_r) * PITCH + k0 + a_c8) * 2;
            LDSM4(ah[mt][0], ah[mt][1], ah[mt][2], ah[mt][3], AhB + aoff);
            LDSM4(al[mt][0], al[mt][1], al[mt][2], al[mt][3], AlB + aoff);
        }
#pragma unroll
        for (int nt = 0; nt < 4; nt++) {
            uint32_t boff = (uint32_t)((k0 + b_k) * PITCH + n0 + nt * 16 + b_n8) * 2;
            uint32_t bh0, bh1, bh2, bh3, bl0, bl1, bl2, bl3;
            LDSM4T(bh0, bh1, bh2, bh3, WhB + boff);
            LDSM4T(bl0, bl1, bl2, bl3, WlB + boff);
#pragma unroll
            for (int mt = 0; mt < 2; mt++) {
                MMA16816(acc[mt][2 * nt],     ah[mt][0], ah[mt][1], ah[mt][2], ah[mt][3], bh0, bh1);
                MMA16816(acc[mt][2 * nt + 1], ah[mt][0], ah[mt][1], ah[mt][2], ah[mt][3], bh2, bh3);
                MMA16816(acc[mt][2 * nt],     ah[mt][0], ah[mt][1], ah[mt][2], ah[mt][3], bl0, bl1);
                MMA16816(acc[mt][2 * nt + 1], ah[mt][0], ah[mt][1], ah[mt][2], ah[mt][3], bl2, bl3);
                MMA16816(acc[mt][2 * nt],     al[mt][0], al[mt][1], al[mt][2], al[mt][3], bh0, bh1);
                MMA16816(acc[mt][2 * nt + 1], al[mt][0], al[mt][1], al[mt][2], al[mt][3], bh2, bh3);
            }
        }
    }

    // ---- epilogue
    int rr = lane >> 2, cc = (lane & 3) * 2;
#pragma unroll
    for (int mt = 0; mt < 2; mt++) {
        int r0 = rowBase + m0 + mt * 16 + rr;
        bool v0 = r0 < NN, v1 = (r0 + 8) < NN;
#pragma unroll
        for (int j = 0; j < 8; j++) {
            int n = n0 + j * 8 + cc;
            if (v0) *(float2*)(C + (size_t)r0 * 128 + n)
                        = make_float2(acc[mt][j][0], acc[mt][j][1]);
            if (v1) *(float2*)(C + (size_t)(r0 + 8) * 128 + n)
                        = make_float2(acc[mt][j][2], acc[mt][j][3]);
        }
    }
}

// ---------------- aggregation 1: conv1 + bias + BN + ELU -> bf16 split -------
__global__ void k_agg1(const float* __restrict__ b0,
                       const float* __restrict__ gamma,
                       const float* __restrict__ beta,
                       const float* __restrict__ mean,
                       const float* __restrict__ var) {
    int i = blockIdx.x;
    int f = threadIdx.x;
    const float* __restrict__ H = g_h;

    float di = g_dis[i];
    float acc0 = di * di * H[i * DD + f];   // self loop
    float acc1 = 0.f, acc2 = 0.f, acc3 = 0.f;

    int s = g_off[i];
    int e = (i + 1 < NN) ? g_off[i + 1] : EE;
    int n = e - s;
    int p = 0;
    for (; p + 4 <= n; p += 4) {
        int   i0 = g_src[s + p + 0], i1 = g_src[s + p + 1];
        int   i2 = g_src[s + p + 2], i3 = g_src[s + p + 3];
        float w0 = g_wn[s + p + 0],  w1 = g_wn[s + p + 1];
        float w2 = g_wn[s + p + 2],  w3 = g_wn[s + p + 3];
        acc0 += w0 * H[i0 * DD + f];
        acc1 += w1 * H[i1 * DD + f];
        acc2 += w2 * H[i2 * DD + f];
        acc3 += w3 * H[i3 * DD + f];
    }
    for (; p < n; p++)
        acc0 += g_wn[s + p] * H[g_src[s + p] * DD + f];

    float acc = ((acc0 + acc1) + (acc2 + acc3)) + b0[f];
    float sc  = gamma[f] * rsqrtf(var[f] + BN_EPS);
    float y   = (acc - mean[f]) * sc + beta[f];
    y = (y > 0.f) ? y : expm1f(y);

    __nv_bfloat16 hi = __float2bfloat16(y);
    float hif = __bfloat162float(hi);
    g_h1h[i * DD + f] = hi;
    g_h1l[i * DD + f] = __float2bfloat16(y - hif);
}

// ---------------- aggregation 2 + final fusion mean --------------------------
__global__ void k_agg2(const float* __restrict__ emb,
                       const float* __restrict__ b1,
                       float* __restrict__ out) {
    int i = blockIdx.x;
    int f = threadIdx.x;
    const float* __restrict__ G = g_g;

    float di = g_dis[i];
    float acc0 = di * di * G[i * DD + f];
    float acc1 = 0.f, acc2 = 0.f, acc3 = 0.f;

    int s = g_off[i];
    int e = (i + 1 < NN) ? g_off[i + 1] : EE;
    int n = e - s;
    int p = 0;
    for (; p + 4 <= n; p += 4) {
        int   i0 = g_src[s + p + 0], i1 = g_src[s + p + 1];
        int   i2 = g_src[s + p + 2], i3 = g_src[s + p + 3];
        float w0 = g_wn[s + p + 0],  w1 = g_wn[s + p + 1];
        float w2 = g_wn[s + p + 2],  w3 = g_wn[s + p + 3];
        acc0 += w0 * G[i0 * DD + f];
        acc1 += w1 * G[i1 * DD + f];
        acc2 += w2 * G[i2 * DD + f];
        acc3 += w3 * G[i3 * DD + f];
    }
    for (; p < n; p++)
        acc0 += g_wn[s + p] * G[g_src[s + p] * DD + f];

    float h2 = ((acc0 + acc1) + (acc2 + acc3)) + b1[f];
    float h1 = __bfloat162float(g_h1h[i * DD + f])
             + __bfloat162float(g_h1l[i * DD + f]);
    out[i * DD + f] = (emb[i * DD + f] + h1 + h2) * (1.0f / 3.0f);
}

// ---------------- launch -----------------------------------------------------
extern "C" void kernel_launch(void* const* d_in, const int* in_sizes, int n_in,
                              void* d_out, int out_size) {
    const float* emb   = (const float*)d_in[0];
    const int*   ei    = (const int*)  d_in[1];
    const float* ew    = (const float*)d_in[2];
    const float* W0    = (const float*)d_in[3];
    const float* b0    = (const float*)d_in[4];
    const float* W1    = (const float*)d_in[5];
    const float* b1    = (const float*)d_in[6];
    const float* gamma = (const float*)d_in[7];
    const float* beta  = (const float*)d_in[8];
    const float* mean  = (const float*)d_in[9];
    const float* var   = (const float*)d_in[10];
    float* out = (float*)d_out;

    const int* row = ei;        // edge_index[0]
    const int* col = ei + EE;   // edge_index[1]

    const int NB_E = (EE + 255) / 256;

    cudaFuncSetAttribute(k_gemm_mma, cudaFuncAttributeMaxDynamicSharedMemorySize, SM_TOT);

    k_split_w<<<32, 256>>>(W0, W1);
    k_deg    <<<NB_E, 256>>>(col, ew);
    k_bsum   <<<NSCAN_BLK, 256>>>();
    k_bscan  <<<1, 256>>>();
    k_scan3  <<<NSCAN_BLK, 256>>>();
    k_scatter<<<NB_E, 256>>>(row, col, ew);

    const int NTILE = (NN + 127) / 128;   // 391
    k_gemm_mma<<<NTILE, 256, SM_TOT>>>(emb, 0);      // g_h = emb @ W0
    k_agg1<<<NN, DD>>>(b0, gamma, beta, mean, var);
    k_gemm_mma<<<NTILE, 256, SM_TOT>>>(nullptr, 1);  // g_g = h1 @ W1
    k_agg2<<<NN, DD>>>(emb, b1, out);
}